// round 1
// baseline (speedup 1.0000x reference)
#include <cuda_runtime.h>

#define KDIM 64
#define MDIM 16
#define TPB 128
#define ROWS_PER_THREAD 4
#define ROWS_PER_BLOCK (TPB * ROWS_PER_THREAD)

typedef unsigned long long u64;

__device__ __forceinline__ u64 pack2(float lo, float hi) {
    u64 r;
    asm("mov.b64 %0, {%1, %2};" : "=l"(r) : "f"(lo), "f"(hi));
    return r;
}

__device__ __forceinline__ void unpack2(u64 v, float& lo, float& hi) {
    asm("mov.b64 {%0, %1}, %2;" : "=f"(lo), "=f"(hi) : "l"(v));
}

__device__ __forceinline__ u64 fma2(u64 a, u64 b, u64 c) {
    u64 d;
    asm("fma.rn.f32x2 %0, %1, %2, %3;" : "=l"(d) : "l"(a), "l"(b), "l"(c));
    return d;
}

__global__ __launch_bounds__(TPB)
void dual_compress_kernel(const float* __restrict__ phi_fwd,
                          const float* __restrict__ phi_bwd,
                          const float* __restrict__ alpha_fwd,
                          const float* __restrict__ alpha_bwd,
                          float* __restrict__ out,
                          int V)
{
    // Duplicated packed weights: sw[k*MDIM + m] = {exp(alpha[m][k]), exp(alpha[m][k])}
    __shared__ u64 sw[KDIM * MDIM];  // 8 KB

    const int side = blockIdx.y;
    const float* __restrict__ phi   = side ? phi_bwd   : phi_fwd;
    const float* __restrict__ alpha = side ? alpha_bwd : alpha_fwd;
    float* __restrict__ y = out + (size_t)side * (size_t)V * MDIM;

    // Build the exp(alpha) table once per block (1024 entries, 8 per thread).
    for (int idx = threadIdx.x; idx < KDIM * MDIM; idx += TPB) {
        int k = idx / MDIM;
        int m = idx % MDIM;
        float w = __expf(alpha[m * KDIM + k]);
        sw[idx] = pack2(w, w);
    }
    __syncthreads();

    // Row assignment: strided so that stores (and loads at fixed i) from
    // consecutive threads hit consecutive rows -> coalesced stores.
    const int base = blockIdx.x * ROWS_PER_BLOCK + threadIdx.x;
    const int r0 = base;
    const int r1 = base + TPB;
    const int r2 = base + 2 * TPB;
    const int r3 = base + 3 * TPB;

    // Clamp load rows for tail blocks (stores are guarded below).
    const int c0 = min(r0, V - 1);
    const int c1 = min(r1, V - 1);
    const int c2 = min(r2, V - 1);
    const int c3 = min(r3, V - 1);

    const float4* __restrict__ p0 = (const float4*)(phi + (size_t)c0 * KDIM);
    const float4* __restrict__ p1 = (const float4*)(phi + (size_t)c1 * KDIM);
    const float4* __restrict__ p2 = (const float4*)(phi + (size_t)c2 * KDIM);
    const float4* __restrict__ p3 = (const float4*)(phi + (size_t)c3 * KDIM);

    u64 acc01[MDIM];
    u64 acc23[MDIM];
#pragma unroll
    for (int m = 0; m < MDIM; ++m) { acc01[m] = 0ull; acc23[m] = 0ull; }

#pragma unroll 2
    for (int kc = 0; kc < KDIM / 4; ++kc) {
        float4 a0 = p0[kc];
        float4 a1 = p1[kc];
        float4 a2 = p2[kc];
        float4 a3 = p3[kc];

        u64 e01[4], e23[4];
        e01[0] = pack2(__expf(a0.x), __expf(a1.x));
        e01[1] = pack2(__expf(a0.y), __expf(a1.y));
        e01[2] = pack2(__expf(a0.z), __expf(a1.z));
        e01[3] = pack2(__expf(a0.w), __expf(a1.w));
        e23[0] = pack2(__expf(a2.x), __expf(a3.x));
        e23[1] = pack2(__expf(a2.y), __expf(a3.y));
        e23[2] = pack2(__expf(a2.z), __expf(a3.z));
        e23[3] = pack2(__expf(a2.w), __expf(a3.w));

        const u64* __restrict__ w = &sw[kc * 4 * MDIM];
#pragma unroll
        for (int j = 0; j < 4; ++j) {
#pragma unroll
            for (int m = 0; m < MDIM; ++m) {
                u64 wv = w[j * MDIM + m];
                acc01[m] = fma2(e01[j], wv, acc01[m]);
                acc23[m] = fma2(e23[j], wv, acc23[m]);
            }
        }
    }

    // Epilogue: y = log(sum), store 16 floats per row as 4x float4.
    float y0[MDIM], y1[MDIM], y2[MDIM], y3[MDIM];
#pragma unroll
    for (int m = 0; m < MDIM; ++m) {
        float s0, s1, s2, s3;
        unpack2(acc01[m], s0, s1);
        unpack2(acc23[m], s2, s3);
        y0[m] = __logf(s0);
        y1[m] = __logf(s1);
        y2[m] = __logf(s2);
        y3[m] = __logf(s3);
    }

    if (r0 < V) {
        float4* o = (float4*)(y + (size_t)r0 * MDIM);
        o[0] = make_float4(y0[0],  y0[1],  y0[2],  y0[3]);
        o[1] = make_float4(y0[4],  y0[5],  y0[6],  y0[7]);
        o[2] = make_float4(y0[8],  y0[9],  y0[10], y0[11]);
        o[3] = make_float4(y0[12], y0[13], y0[14], y0[15]);
    }
    if (r1 < V) {
        float4* o = (float4*)(y + (size_t)r1 * MDIM);
        o[0] = make_float4(y1[0],  y1[1],  y1[2],  y1[3]);
        o[1] = make_float4(y1[4],  y1[5],  y1[6],  y1[7]);
        o[2] = make_float4(y1[8],  y1[9],  y1[10], y1[11]);
        o[3] = make_float4(y1[12], y1[13], y1[14], y1[15]);
    }
    if (r2 < V) {
        float4* o = (float4*)(y + (size_t)r2 * MDIM);
        o[0] = make_float4(y2[0],  y2[1],  y2[2],  y2[3]);
        o[1] = make_float4(y2[4],  y2[5],  y2[6],  y2[7]);
        o[2] = make_float4(y2[8],  y2[9],  y2[10], y2[11]);
        o[3] = make_float4(y2[12], y2[13], y2[14], y2[15]);
    }
    if (r3 < V) {
        float4* o = (float4*)(y + (size_t)r3 * MDIM);
        o[0] = make_float4(y3[0],  y3[1],  y3[2],  y3[3]);
        o[1] = make_float4(y3[4],  y3[5],  y3[6],  y3[7]);
        o[2] = make_float4(y3[8],  y3[9],  y3[10], y3[11]);
        o[3] = make_float4(y3[12], y3[13], y3[14], y3[15]);
    }
}

extern "C" void kernel_launch(void* const* d_in, const int* in_sizes, int n_in,
                              void* d_out, int out_size)
{
    const float* d_out_t   = (const float*)d_in[0];  // (V, 64) fwd phi
    const float* d_in_t    = (const float*)d_in[1];  // (V, 64) bwd phi
    const float* alpha_fwd = (const float*)d_in[2];  // (16, 64)
    const float* alpha_bwd = (const float*)d_in[3];  // (16, 64)
    float* out = (float*)d_out;                      // [y_fwd (V,16) | y_bwd (V,16)]

    const int V = in_sizes[0] / KDIM;

    dim3 grid((V + ROWS_PER_BLOCK - 1) / ROWS_PER_BLOCK, 2);
    dual_compress_kernel<<<grid, TPB>>>(d_out_t, d_in_t, alpha_fwd, alpha_bwd, out, V);
}

// round 2
// speedup vs baseline: 1.1311x; 1.1311x over previous
#include <cuda_runtime.h>

#define KDIM 64
#define MDIM 16
#define MP   (MDIM / 2)        // 8 m-pairs
#define TPB  128
#define ROWS_PER_THREAD 2
#define ROWS_PER_BLOCK (TPB * ROWS_PER_THREAD)

typedef unsigned long long u64;

__device__ __forceinline__ u64 pack2(float lo, float hi) {
    u64 r;
    asm("mov.b64 %0, {%1, %2};" : "=l"(r) : "f"(lo), "f"(hi));
    return r;
}

__device__ __forceinline__ void unpack2(u64 v, float& lo, float& hi) {
    asm("mov.b64 {%0, %1}, %2;" : "=f"(lo), "=f"(hi) : "l"(v));
}

__device__ __forceinline__ u64 fma2(u64 a, u64 b, u64 c) {
    u64 d;
    asm("fma.rn.f32x2 %0, %1, %2, %3;" : "=l"(d) : "l"(a), "l"(b), "l"(c));
    return d;
}

__global__ __launch_bounds__(TPB, 6)
void dual_compress_kernel(const float* __restrict__ phi_fwd,
                          const float* __restrict__ phi_bwd,
                          const float* __restrict__ alpha_fwd,
                          const float* __restrict__ alpha_bwd,
                          float* __restrict__ out,
                          int V)
{
    // m-pair packed weights: sw[k][mp] = {exp(alpha[2mp][k]), exp(alpha[2mp+1][k])}
    // 64 * 8 * 8B = 4 KB, 16B-aligned rows for LDS.128.
    __shared__ ulonglong2 sw[KDIM * MP / 2];   // viewed as u64[KDIM*MP]
    u64* swf = (u64*)sw;

    const int side = blockIdx.y;
    const float* __restrict__ phi   = side ? phi_bwd   : phi_fwd;
    const float* __restrict__ alpha = side ? alpha_bwd : alpha_fwd;
    float* __restrict__ y = out + (size_t)side * (size_t)V * MDIM;

    // Build exp(alpha) table: 512 u64 entries, 4 per thread.
    for (int idx = threadIdx.x; idx < KDIM * MP; idx += TPB) {
        int k  = idx / MP;
        int mp = idx % MP;
        float w0 = __expf(alpha[(2 * mp)     * KDIM + k]);
        float w1 = __expf(alpha[(2 * mp + 1) * KDIM + k]);
        swf[idx] = pack2(w0, w1);
    }
    __syncthreads();

    const int base = blockIdx.x * ROWS_PER_BLOCK + threadIdx.x;
    const int r0 = base;
    const int r1 = base + TPB;
    const int c0 = min(r0, V - 1);
    const int c1 = min(r1, V - 1);

    const float4* __restrict__ p0 = (const float4*)(phi + (size_t)c0 * KDIM);
    const float4* __restrict__ p1 = (const float4*)(phi + (size_t)c1 * KDIM);

    u64 acc0[MP];  // row r0: {y[2mp], y[2mp+1]}
    u64 acc1[MP];  // row r1
#pragma unroll
    for (int mp = 0; mp < MP; ++mp) { acc0[mp] = 0ull; acc1[mp] = 0ull; }

#pragma unroll 4
    for (int kc = 0; kc < KDIM / 4; ++kc) {
        float4 a0 = p0[kc];
        float4 a1 = p1[kc];

        float e0[4], e1[4];
        e0[0] = __expf(a0.x); e0[1] = __expf(a0.y); e0[2] = __expf(a0.z); e0[3] = __expf(a0.w);
        e1[0] = __expf(a1.x); e1[1] = __expf(a1.y); e1[2] = __expf(a1.z); e1[3] = __expf(a1.w);

#pragma unroll
        for (int j = 0; j < 4; ++j) {
            const int k = kc * 4 + j;
            u64 E0 = pack2(e0[j], e0[j]);
            u64 E1 = pack2(e1[j], e1[j]);

            // 4x LDS.128 = 8 weight pairs for this k, reused by both rows.
            ulonglong2 w01 = sw[k * (MP / 2) + 0];
            ulonglong2 w23 = sw[k * (MP / 2) + 1];
            ulonglong2 w45 = sw[k * (MP / 2) + 2];
            ulonglong2 w67 = sw[k * (MP / 2) + 3];

            acc0[0] = fma2(E0, w01.x, acc0[0]);
            acc0[1] = fma2(E0, w01.y, acc0[1]);
            acc0[2] = fma2(E0, w23.x, acc0[2]);
            acc0[3] = fma2(E0, w23.y, acc0[3]);
            acc0[4] = fma2(E0, w45.x, acc0[4]);
            acc0[5] = fma2(E0, w45.y, acc0[5]);
            acc0[6] = fma2(E0, w67.x, acc0[6]);
            acc0[7] = fma2(E0, w67.y, acc0[7]);

            acc1[0] = fma2(E1, w01.x, acc1[0]);
            acc1[1] = fma2(E1, w01.y, acc1[1]);
            acc1[2] = fma2(E1, w23.x, acc1[2]);
            acc1[3] = fma2(E1, w23.y, acc1[3]);
            acc1[4] = fma2(E1, w45.x, acc1[4]);
            acc1[5] = fma2(E1, w45.y, acc1[5]);
            acc1[6] = fma2(E1, w67.x, acc1[6]);
            acc1[7] = fma2(E1, w67.y, acc1[7]);
        }
    }

    // Epilogue: y = log(sum), 16 floats per row as 4x float4.
    float y0[MDIM], y1[MDIM];
#pragma unroll
    for (int mp = 0; mp < MP; ++mp) {
        float s0a, s0b, s1a, s1b;
        unpack2(acc0[mp], s0a, s0b);
        unpack2(acc1[mp], s1a, s1b);
        y0[2 * mp] = __logf(s0a); y0[2 * mp + 1] = __logf(s0b);
        y1[2 * mp] = __logf(s1a); y1[2 * mp + 1] = __logf(s1b);
    }

    if (r0 < V) {
        float4* o = (float4*)(y + (size_t)r0 * MDIM);
        o[0] = make_float4(y0[0],  y0[1],  y0[2],  y0[3]);
        o[1] = make_float4(y0[4],  y0[5],  y0[6],  y0[7]);
        o[2] = make_float4(y0[8],  y0[9],  y0[10], y0[11]);
        o[3] = make_float4(y0[12], y0[13], y0[14], y0[15]);
    }
    if (r1 < V) {
        float4* o = (float4*)(y + (size_t)r1 * MDIM);
        o[0] = make_float4(y1[0],  y1[1],  y1[2],  y1[3]);
        o[1] = make_float4(y1[4],  y1[5],  y1[6],  y1[7]);
        o[2] = make_float4(y1[8],  y1[9],  y1[10], y1[11]);
        o[3] = make_float4(y1[12], y1[13], y1[14], y1[15]);
    }
}

extern "C" void kernel_launch(void* const* d_in, const int* in_sizes, int n_in,
                              void* d_out, int out_size)
{
    const float* d_out_t   = (const float*)d_in[0];  // (V, 64) fwd phi
    const float* d_in_t    = (const float*)d_in[1];  // (V, 64) bwd phi
    const float* alpha_fwd = (const float*)d_in[2];  // (16, 64)
    const float* alpha_bwd = (const float*)d_in[3];  // (16, 64)
    float* out = (float*)d_out;                      // [y_fwd (V,16) | y_bwd (V,16)]

    const int V = in_sizes[0] / KDIM;

    dim3 grid((V + ROWS_PER_BLOCK - 1) / ROWS_PER_BLOCK, 2);
    dual_compress_kernel<<<grid, TPB>>>(d_out_t, d_in_t, alpha_fwd, alpha_bwd, out, V);
}

// round 3
// speedup vs baseline: 1.3177x; 1.1651x over previous
#include <cuda_runtime.h>

#define KDIM 64
#define MDIM 16
#define MP   8                 // m-pairs
#define TPB  128
#define RPT  2
#define RPB  (TPB * RPT)       // 256 rows per block
#define KC   32                // k-chunk staged per pass
#define TSTRIDE 36             // floats per tile row (32 data + 4 pad, 144B: 16B-aligned, conflict-free)

typedef unsigned long long u64;

__device__ __forceinline__ u64 pack2(float lo, float hi) {
    u64 r;
    asm("mov.b64 %0, {%1, %2};" : "=l"(r) : "f"(lo), "f"(hi));
    return r;
}

__device__ __forceinline__ void unpack2(u64 v, float& lo, float& hi) {
    asm("mov.b64 {%0, %1}, %2;" : "=f"(lo), "=f"(hi) : "l"(v));
}

__device__ __forceinline__ u64 fma2(u64 a, u64 b, u64 c) {
    u64 d;
    asm("fma.rn.f32x2 %0, %1, %2, %3;" : "=l"(d) : "l"(a), "l"(b), "l"(c));
    return d;
}

__global__ __launch_bounds__(TPB, 5)
void dual_compress_kernel(const float* __restrict__ phi_fwd,
                          const float* __restrict__ phi_bwd,
                          const float* __restrict__ alpha_fwd,
                          const float* __restrict__ alpha_bwd,
                          float* __restrict__ out,
                          int V)
{
    __shared__ float tile[RPB * TSTRIDE];          // 36,864 B
    __shared__ ulonglong2 sw2[KDIM * MP / 2];      //  4,096 B
    u64* swf = (u64*)sw2;

    const int side = blockIdx.y;
    const float* __restrict__ phi   = side ? phi_bwd   : phi_fwd;
    const float* __restrict__ alpha = side ? alpha_bwd : alpha_fwd;
    float* __restrict__ y = out + (size_t)side * (size_t)V * MDIM;

    // Weight table: sw[k][mp] = {exp(alpha[2mp][k]), exp(alpha[2mp+1][k])}
    for (int idx = threadIdx.x; idx < KDIM * MP; idx += TPB) {
        int k  = idx / MP;
        int mp = idx % MP;
        float w0 = __expf(alpha[(2 * mp)     * KDIM + k]);
        float w1 = __expf(alpha[(2 * mp + 1) * KDIM + k]);
        swf[idx] = pack2(w0, w1);
    }

    const int blockRow = blockIdx.x * RPB;
    const int r0 = blockRow + threadIdx.x;
    const int r1 = r0 + TPB;

    u64 acc0[MP], acc1[MP];
#pragma unroll
    for (int mp = 0; mp < MP; ++mp) { acc0[mp] = 0ull; acc1[mp] = 0ull; }

    const float4* __restrict__ t0 = (const float4*)&tile[threadIdx.x * TSTRIDE];
    const float4* __restrict__ t1 = (const float4*)&tile[(threadIdx.x + TPB) * TSTRIDE];

    for (int ch = 0; ch < KDIM / KC; ++ch) {
        __syncthreads();   // tile free (prev compute done); also orders weight build at ch=0

        // Stage chunk: 256 rows x 32 floats, fully coalesced.
        // idx -> (row = idx/8, c4 = idx%8); warp covers 4 rows x 128B = 4 full lines.
#pragma unroll
        for (int i = 0; i < (RPB * KC / 4) / TPB; ++i) {      // 16 iters
            int idx  = threadIdx.x + i * TPB;
            int row  = idx >> 3;
            int c4   = idx & 7;
            int grow = min(blockRow + row, V - 1);
            float4 v = *(const float4*)(phi + (size_t)grow * KDIM + ch * KC + c4 * 4);
            *(float4*)&tile[row * TSTRIDE + c4 * 4] = v;
        }
        __syncthreads();

#pragma unroll
        for (int j4 = 0; j4 < KC / 4; ++j4) {                 // 8 iters
            float4 a0 = t0[j4];
            float4 a1 = t1[j4];

            float e0[4], e1[4];
            e0[0] = __expf(a0.x); e0[1] = __expf(a0.y); e0[2] = __expf(a0.z); e0[3] = __expf(a0.w);
            e1[0] = __expf(a1.x); e1[1] = __expf(a1.y); e1[2] = __expf(a1.z); e1[3] = __expf(a1.w);

            const int kbase = ch * KC + j4 * 4;
#pragma unroll
            for (int j = 0; j < 4; ++j) {
                const int k = kbase + j;
                u64 E0 = pack2(e0[j], e0[j]);
                u64 E1 = pack2(e1[j], e1[j]);

                ulonglong2 w01 = sw2[k * 4 + 0];
                ulonglong2 w23 = sw2[k * 4 + 1];
                ulonglong2 w45 = sw2[k * 4 + 2];
                ulonglong2 w67 = sw2[k * 4 + 3];

                acc0[0] = fma2(E0, w01.x, acc0[0]);
                acc1[0] = fma2(E1, w01.x, acc1[0]);
                acc0[1] = fma2(E0, w01.y, acc0[1]);
                acc1[1] = fma2(E1, w01.y, acc1[1]);
                acc0[2] = fma2(E0, w23.x, acc0[2]);
                acc1[2] = fma2(E1, w23.x, acc1[2]);
                acc0[3] = fma2(E0, w23.y, acc0[3]);
                acc1[3] = fma2(E1, w23.y, acc1[3]);
                acc0[4] = fma2(E0, w45.x, acc0[4]);
                acc1[4] = fma2(E1, w45.x, acc1[4]);
                acc0[5] = fma2(E0, w45.y, acc0[5]);
                acc1[5] = fma2(E1, w45.y, acc1[5]);
                acc0[6] = fma2(E0, w67.x, acc0[6]);
                acc1[6] = fma2(E1, w67.x, acc1[6]);
                acc0[7] = fma2(E0, w67.y, acc0[7]);
                acc1[7] = fma2(E1, w67.y, acc1[7]);
            }
        }
    }

    // Epilogue: y = log(sum)
    float y0[MDIM], y1[MDIM];
#pragma unroll
    for (int mp = 0; mp < MP; ++mp) {
        float s0a, s0b, s1a, s1b;
        unpack2(acc0[mp], s0a, s0b);
        unpack2(acc1[mp], s1a, s1b);
        y0[2 * mp] = __logf(s0a); y0[2 * mp + 1] = __logf(s0b);
        y1[2 * mp] = __logf(s1a); y1[2 * mp + 1] = __logf(s1b);
    }

    if (r0 < V) {
        float4* o = (float4*)(y + (size_t)r0 * MDIM);
        o[0] = make_float4(y0[0],  y0[1],  y0[2],  y0[3]);
        o[1] = make_float4(y0[4],  y0[5],  y0[6],  y0[7]);
        o[2] = make_float4(y0[8],  y0[9],  y0[10], y0[11]);
        o[3] = make_float4(y0[12], y0[13], y0[14], y0[15]);
    }
    if (r1 < V) {
        float4* o = (float4*)(y + (size_t)r1 * MDIM);
        o[0] = make_float4(y1[0],  y1[1],  y1[2],  y1[3]);
        o[1] = make_float4(y1[4],  y1[5],  y1[6],  y1[7]);
        o[2] = make_float4(y1[8],  y1[9],  y1[10], y1[11]);
        o[3] = make_float4(y1[12], y1[13], y1[14], y1[15]);
    }
}

extern "C" void kernel_launch(void* const* d_in, const int* in_sizes, int n_in,
                              void* d_out, int out_size)
{
    const float* d_out_t   = (const float*)d_in[0];  // (V, 64) fwd phi
    const float* d_in_t    = (const float*)d_in[1];  // (V, 64) bwd phi
    const float* alpha_fwd = (const float*)d_in[2];  // (16, 64)
    const float* alpha_bwd = (const float*)d_in[3];  // (16, 64)
    float* out = (float*)d_out;                      // [y_fwd (V,16) | y_bwd (V,16)]

    const int V = in_sizes[0] / KDIM;

    dim3 grid((V + RPB - 1) / RPB, 2);
    dual_compress_kernel<<<grid, TPB>>>(d_out_t, d_in_t, alpha_fwd, alpha_bwd, out, V);
}

// round 5
// speedup vs baseline: 1.3324x; 1.0111x over previous
#include <cuda_runtime.h>
#include <cstdint>

#define KDIM 64
#define MDIM 16
#define MP   8                  // m-pairs
#define TPB  128
#define RPT  2
#define RPB  (TPB * RPT)        // 256 rows per block
#define KC   16                 // k-chunk per pipeline stage
#define NCH  (KDIM / KC)        // 4 chunks
#define TSTRIDE 20              // floats per tile row (16 data + 4 pad) -> conflict-free LDS.128
#define TILE_ELEMS (RPB * TSTRIDE)

typedef unsigned long long u64;
typedef unsigned int u32;

__device__ __forceinline__ u64 pack2(float lo, float hi) {
    u64 r;
    asm("mov.b64 %0, {%1, %2};" : "=l"(r) : "f"(lo), "f"(hi));
    return r;
}

__device__ __forceinline__ void unpack2(u64 v, float& lo, float& hi) {
    asm("mov.b64 {%0, %1}, %2;" : "=f"(lo), "=f"(hi) : "l"(v));
}

__device__ __forceinline__ u64 fma2(u64 a, u64 b, u64 c) {
    u64 d;
    asm("fma.rn.f32x2 %0, %1, %2, %3;" : "=l"(d) : "l"(a), "l"(b), "l"(c));
    return d;
}

__device__ __forceinline__ void cp16(u32 smem_dst, const void* gsrc) {
    asm volatile("cp.async.cg.shared.global [%0], [%1], 16;\n"
                 :: "r"(smem_dst), "l"(gsrc));
}
__device__ __forceinline__ void cp_commit() {
    asm volatile("cp.async.commit_group;\n");
}
template <int N>
__device__ __forceinline__ void cp_wait() {
    asm volatile("cp.async.wait_group %0;\n" :: "n"(N));
}

__global__ __launch_bounds__(TPB, 5)
void dual_compress_kernel(const float* __restrict__ phi_fwd,
                          const float* __restrict__ phi_bwd,
                          const float* __restrict__ alpha_fwd,
                          const float* __restrict__ alpha_bwd,
                          float* __restrict__ out,
                          int V)
{
    __shared__ float tile[2][TILE_ELEMS];          // 2 x 20,480 B
    __shared__ ulonglong2 sw2[KDIM * MP / 2];      // 4,096 B
    u64* swf = (u64*)sw2;

    const int side = blockIdx.y;
    const float* __restrict__ phi   = side ? phi_bwd   : phi_fwd;
    const float* __restrict__ alpha = side ? alpha_bwd : alpha_fwd;
    float* __restrict__ y = out + (size_t)side * (size_t)V * MDIM;

    const int blockRow = blockIdx.x * RPB;
    const int tid = threadIdx.x;

    // ---- kick off stage of chunks 0 and 1 FIRST (hide DRAM latency behind weight build)
    // staging decomposition: idx in [0, RPB*KC/4): row = idx>>2, c4 = idx&3
    u32 tbase0 = (u32)__cvta_generic_to_shared(&tile[0][0]);
    u32 tbase1 = (u32)__cvta_generic_to_shared(&tile[1][0]);

#pragma unroll
    for (int buf = 0; buf < 2; ++buf) {
        const int ch = buf;
        const u32 tb = buf ? tbase1 : tbase0;
#pragma unroll
        for (int i = 0; i < (RPB * KC / 4) / TPB; ++i) {   // 8 iters
            int idx  = tid + i * TPB;
            int row  = idx >> 2;
            int c4   = idx & 3;
            int grow = min(blockRow + row, V - 1);
            cp16(tb + (u32)(row * TSTRIDE + c4 * 4) * 4u,
                 phi + (size_t)grow * KDIM + ch * KC + c4 * 4);
        }
        cp_commit();
    }

    // ---- weight table while loads are in flight
    for (int idx = tid; idx < KDIM * MP; idx += TPB) {
        int k  = idx / MP;
        int mp = idx % MP;
        float w0 = __expf(alpha[(2 * mp)     * KDIM + k]);
        float w1 = __expf(alpha[(2 * mp + 1) * KDIM + k]);
        swf[idx] = pack2(w0, w1);
    }

    const int r0 = blockRow + tid;
    const int r1 = r0 + TPB;

    u64 acc0[MP], acc1[MP];
#pragma unroll
    for (int mp = 0; mp < MP; ++mp) { acc0[mp] = 0ull; acc1[mp] = 0ull; }

#pragma unroll
    for (int ch = 0; ch < NCH; ++ch) {
        if (ch == NCH - 1) cp_wait<0>(); else cp_wait<1>();
        __syncthreads();   // chunk `ch` buffer filled & visible CTA-wide; weights ready (ch==0)

        const int buf = ch & 1;
        const float4* __restrict__ t0 = (const float4*)&tile[buf][tid * TSTRIDE];
        const float4* __restrict__ t1 = (const float4*)&tile[buf][(tid + TPB) * TSTRIDE];

#pragma unroll
        for (int j4 = 0; j4 < KC / 4; ++j4) {              // 4 iters
            float4 a0 = t0[j4];
            float4 a1 = t1[j4];

            float e0[4], e1[4];
            e0[0] = __expf(a0.x); e0[1] = __expf(a0.y); e0[2] = __expf(a0.z); e0[3] = __expf(a0.w);
            e1[0] = __expf(a1.x); e1[1] = __expf(a1.y); e1[2] = __expf(a1.z); e1[3] = __expf(a1.w);

            const int kbase = ch * KC + j4 * 4;
#pragma unroll
            for (int j = 0; j < 4; ++j) {
                const int k = kbase + j;
                u64 E0 = pack2(e0[j], e0[j]);
                u64 E1 = pack2(e1[j], e1[j]);

                ulonglong2 w01 = sw2[k * 4 + 0];
                ulonglong2 w23 = sw2[k * 4 + 1];
                ulonglong2 w45 = sw2[k * 4 + 2];
                ulonglong2 w67 = sw2[k * 4 + 3];

                acc0[0] = fma2(E0, w01.x, acc0[0]);
                acc1[0] = fma2(E1, w01.x, acc1[0]);
                acc0[1] = fma2(E0, w01.y, acc0[1]);
                acc1[1] = fma2(E1, w01.y, acc1[1]);
                acc0[2] = fma2(E0, w23.x, acc0[2]);
                acc1[2] = fma2(E1, w23.x, acc1[2]);
                acc0[3] = fma2(E0, w23.y, acc0[3]);
                acc1[3] = fma2(E1, w23.y, acc1[3]);
                acc0[4] = fma2(E0, w45.x, acc0[4]);
                acc1[4] = fma2(E1, w45.x, acc1[4]);
                acc0[5] = fma2(E0, w45.y, acc0[5]);
                acc1[5] = fma2(E1, w45.y, acc1[5]);
                acc0[6] = fma2(E0, w67.x, acc0[6]);
                acc1[6] = fma2(E1, w67.x, acc1[6]);
                acc0[7] = fma2(E0, w67.y, acc0[7]);
                acc1[7] = fma2(E1, w67.y, acc1[7]);
            }
        }

        // restage this buffer with chunk ch+2 (if any)
        if (ch + 2 < NCH) {
            __syncthreads();   // everyone done reading tile[buf]
            const int nch = ch + 2;
            const u32 tb = buf ? tbase1 : tbase0;
#pragma unroll
            for (int i = 0; i < (RPB * KC / 4) / TPB; ++i) {
                int idx  = tid + i * TPB;
                int row  = idx >> 2;
                int c4   = idx & 3;
                int grow = min(blockRow + row, V - 1);
                cp16(tb + (u32)(row * TSTRIDE + c4 * 4) * 4u,
                     phi + (size_t)grow * KDIM + nch * KC + c4 * 4);
            }
            cp_commit();
        }
    }

    // ---- epilogue: y = log(sum)
    float y0[MDIM], y1[MDIM];
#pragma unroll
    for (int mp = 0; mp < MP; ++mp) {
        float s0a, s0b, s1a, s1b;
        unpack2(acc0[mp], s0a, s0b);
        unpack2(acc1[mp], s1a, s1b);
        y0[2 * mp] = __logf(s0a); y0[2 * mp + 1] = __logf(s0b);
        y1[2 * mp] = __logf(s1a); y1[2 * mp + 1] = __logf(s1b);
    }

    if (r0 < V) {
        float4* o = (float4*)(y + (size_t)r0 * MDIM);
        o[0] = make_float4(y0[0],  y0[1],  y0[2],  y0[3]);
        o[1] = make_float4(y0[4],  y0[5],  y0[6],  y0[7]);
        o[2] = make_float4(y0[8],  y0[9],  y0[10], y0[11]);
        o[3] = make_float4(y0[12], y0[13], y0[14], y0[15]);
    }
    if (r1 < V) {
        float4* o = (float4*)(y + (size_t)r1 * MDIM);
        o[0] = make_float4(y1[0],  y1[1],  y1[2],  y1[3]);
        o[1] = make_float4(y1[4],  y1[5],  y1[6],  y1[7]);
        o[2] = make_float4(y1[8],  y1[9],  y1[10], y1[11]);
        o[3] = make_float4(y1[12], y1[13], y1[14], y1[15]);
    }
}

extern "C" void kernel_launch(void* const* d_in, const int* in_sizes, int n_in,
                              void* d_out, int out_size)
{
    const float* d_out_t   = (const float*)d_in[0];  // (V, 64) fwd phi
    const float* d_in_t    = (const float*)d_in[1];  // (V, 64) bwd phi
    const float* alpha_fwd = (const float*)d_in[2];  // (16, 64)
    const float* alpha_bwd = (const float*)d_in[3];  // (16, 64)
    float* out = (float*)d_out;                      // [y_fwd (V,16) | y_bwd (V,16)]

    const int V = in_sizes[0] / KDIM;

    dim3 grid((V + RPB - 1) / RPB, 2);
    dual_compress_kernel<<<grid, TPB>>>(d_out_t, d_in_t, alpha_fwd, alpha_bwd, out, V);
}